// round 1
// baseline (speedup 1.0000x reference)
#include <cuda_runtime.h>

// VectorQuantizer: z (32,256,32,32) f32, codebook (8192,256) f32.
// z.reshape(-1,256): 32768 rows x 256. Outputs (assumed concatenated, f32):
//   [0, 8388608)          z_q_st  (numerically == gathered codebook rows, but
//                         computed as fl(z + fl(z_q - z)) to match reference)
//   [8388608]             loss = 1.25 * mean((z_q - z)^2)
//   [8388609, 8421377)    argmin indices as float
//
// Core: d = (||z||^2 + ||e||^2) - 2*z.e  per (row, code), argmin over 8192
// codes with first-index tie-break (matches jnp.argmin). All rounding done
// with explicit __fadd_rn/__fmaf_rn to mimic the fp32 reference expansion.

#define M_ROWS   32768
#define K_CODES  8192
#define D_DIM    256
#define ZQ_ELEMS (M_ROWS * D_DIM)      /* 8388608 */
#define LOSS_OFF ZQ_ELEMS
#define IDX_OFF  (ZQ_ELEMS + 1)

#define TM 64
#define TN 64
#define TK 16
#define APAD 68   /* row stride in floats: 16B-aligned, avoids 16-way store conflicts */

__device__ float  g_znorm[M_ROWS];
__device__ float  g_enorm[K_CODES];
__device__ int    g_idx[M_ROWS];
__device__ double g_loss_acc;

// ---------------------------------------------------------------------------
// K1: row norms for z and codebook (one warp per row), zero loss accumulator.
// ---------------------------------------------------------------------------
__global__ void vq_norms_kernel(const float* __restrict__ z,
                                const float* __restrict__ cb) {
    int gw   = (blockIdx.x * blockDim.x + threadIdx.x) >> 5;
    int lane = threadIdx.x & 31;
    if (gw == 0 && lane == 0) g_loss_acc = 0.0;
    if (gw >= M_ROWS + K_CODES) return;

    const float* src = (gw < M_ROWS)
                     ? (z  + (size_t)gw * D_DIM)
                     : (cb + (size_t)(gw - M_ROWS) * D_DIM);
    float s = 0.f;
#pragma unroll
    for (int i = 0; i < D_DIM / 32; ++i) {
        float v = src[lane + i * 32];
        s = __fmaf_rn(v, v, s);
    }
#pragma unroll
    for (int off = 16; off > 0; off >>= 1)
        s = __fadd_rn(s, __shfl_xor_sync(0xffffffffu, s, off));
    if (lane == 0) {
        if (gw < M_ROWS) g_znorm[gw] = s;
        else             g_enorm[gw - M_ROWS] = s;
    }
}

// ---------------------------------------------------------------------------
// K2: tiled fp32 GEMM (z_flat @ codebook^T) fused with running argmin.
// CTA owns TM=64 rows, scans all K_CODES in TN=64 tiles, D in TK=16 chunks.
// Thread (tx,ty) of 16x16 grid computes a 4x4 micro-tile:
//   rows = rowBase + ty*4 + i, codes = ct*64 + tx*4 + j.
// ---------------------------------------------------------------------------
__global__ __launch_bounds__(256, 4) void vq_argmin_kernel(
        const float* __restrict__ z, const float* __restrict__ cb) {
    __shared__ float As[TK][APAD];
    __shared__ float Bs[TK][APAD];

    const int t  = threadIdx.x;
    const int tx = t & 15, ty = t >> 4;
    const int rowBase = blockIdx.x * TM;

    float zn[4], bestV[4];
    int   bestI[4];
#pragma unroll
    for (int i = 0; i < 4; ++i) {
        zn[i]    = g_znorm[rowBase + ty * 4 + i];
        bestV[i] = 3.4028235e38f;
        bestI[i] = 0;
    }

    for (int ct = 0; ct < K_CODES / TN; ++ct) {
        float acc[4][4];
#pragma unroll
        for (int i = 0; i < 4; ++i)
#pragma unroll
            for (int j = 0; j < 4; ++j) acc[i][j] = 0.f;

        for (int db = 0; db < D_DIM / TK; ++db) {
            // cooperative load of A (64x16) and B (64x16) chunks, transposed
#pragma unroll
            for (int j = 0; j < 4; ++j) {
                int i = t + j * 256;
                int r = i >> 4, d = i & 15;
                As[d][r] = z [(size_t)(rowBase + r)  * D_DIM + db * TK + d];
                Bs[d][r] = cb[(size_t)(ct * TN + r)  * D_DIM + db * TK + d];
            }
            __syncthreads();
#pragma unroll
            for (int d = 0; d < TK; ++d) {
                float4 a4 = *reinterpret_cast<const float4*>(&As[d][ty * 4]);
                float4 b4 = *reinterpret_cast<const float4*>(&Bs[d][tx * 4]);
                float av[4] = {a4.x, a4.y, a4.z, a4.w};
                float bv[4] = {b4.x, b4.y, b4.z, b4.w};
#pragma unroll
                for (int i = 0; i < 4; ++i)
#pragma unroll
                    for (int j = 0; j < 4; ++j)
                        acc[i][j] = __fmaf_rn(av[i], bv[j], acc[i][j]);
            }
            __syncthreads();
        }

        // d = (||z||^2 + ||e||^2) - 2*dot, reference association; strict <
        // keeps the earliest code (codes iterate ascending per thread).
#pragma unroll
        for (int j = 0; j < 4; ++j) {
            int   c  = ct * TN + tx * 4 + j;
            float en = g_enorm[c];
#pragma unroll
            for (int i = 0; i < 4; ++i) {
                float dv = __fmaf_rn(-2.f, acc[i][j], __fadd_rn(zn[i], en));
                if (dv < bestV[i]) { bestV[i] = dv; bestI[i] = c; }
            }
        }
    }

    // reduce across the 16 code-lanes sharing each row group (shfl width 16);
    // tie-break on smaller index to match jnp.argmin.
#pragma unroll
    for (int off = 8; off > 0; off >>= 1) {
#pragma unroll
        for (int i = 0; i < 4; ++i) {
            float ov = __shfl_down_sync(0xffffffffu, bestV[i], off, 16);
            int   oi = __shfl_down_sync(0xffffffffu, bestI[i], off, 16);
            if (ov < bestV[i] || (ov == bestV[i] && oi < bestI[i])) {
                bestV[i] = ov; bestI[i] = oi;
            }
        }
    }
    if (tx == 0) {
#pragma unroll
        for (int i = 0; i < 4; ++i)
            g_idx[rowBase + ty * 4 + i] = bestI[i];
    }
}

// ---------------------------------------------------------------------------
// K3: gather z_q, write straight-through output, accumulate loss, write idx.
// One block (256 threads) per row; one element per thread.
// ---------------------------------------------------------------------------
__global__ void vq_gather_kernel(const float* __restrict__ z,
                                 const float* __restrict__ cb,
                                 float* __restrict__ out, int out_size) {
    int row = blockIdx.x;
    int t   = threadIdx.x;
    int idx = g_idx[row];

    float zq   = cb[(size_t)idx * D_DIM + t];
    float zv   = z [(size_t)row * D_DIM + t];
    float diff = __fadd_rn(zq, -zv);                 // fl(z_q - z)
    out[(size_t)row * D_DIM + t] = __fadd_rn(zv, diff);  // fl(z + fl(z_q - z))

    float sq = __fmul_rn(diff, diff);
#pragma unroll
    for (int off = 16; off > 0; off >>= 1)
        sq += __shfl_xor_sync(0xffffffffu, sq, off);

    __shared__ float warpS[8];
    if ((t & 31) == 0) warpS[t >> 5] = sq;
    __syncthreads();
    if (t == 0) {
        float s = 0.f;
#pragma unroll
        for (int w = 0; w < 8; ++w) s += warpS[w];
        atomicAdd(&g_loss_acc, (double)s);
        if (IDX_OFF + row < out_size) out[IDX_OFF + row] = (float)idx;
    }
}

// ---------------------------------------------------------------------------
// K4: finalize loss = mean + 0.25*mean = 1.25*mean((z_q - z)^2)
// ---------------------------------------------------------------------------
__global__ void vq_finalize_kernel(float* __restrict__ out, int out_size) {
    if (LOSS_OFF < out_size)
        out[LOSS_OFF] = (float)(1.25 * g_loss_acc / (double)ZQ_ELEMS);
}

// ---------------------------------------------------------------------------
extern "C" void kernel_launch(void* const* d_in, const int* in_sizes, int n_in,
                              void* d_out, int out_size) {
    const float* z  = (const float*)d_in[0];
    const float* cb = (const float*)d_in[1];
    // defensive: if metadata order is (codebook, z), swap by size
    if (n_in >= 2 && in_sizes[0] == K_CODES * D_DIM && in_sizes[1] == ZQ_ELEMS) {
        const float* tmp = z; z = cb; cb = tmp;
    }
    float* out = (float*)d_out;

    int nwarps = M_ROWS + K_CODES;
    vq_norms_kernel  <<<(nwarps * 32 + 255) / 256, 256>>>(z, cb);
    vq_argmin_kernel <<<M_ROWS / TM, 256>>>(z, cb);
    vq_gather_kernel <<<M_ROWS, 256>>>(z, cb, out, out_size);
    vq_finalize_kernel<<<1, 1>>>(out, out_size);
}